// round 17
// baseline (speedup 1.0000x reference)
#include <cuda_runtime.h>
#include <cuda_bf16.h>
#include <cstdint>

// ---------------------------------------------------------------------------
// Round 17: q softmax distributed into GEMMs.
//   qkv = x @ Wqkv^T -> eq=exp(q) | Eth=exp(k)^T | Vth=v^T   (OM=6)
//   rcp[b,d]  = 1/rowsum(Eth)          (folded into reduce_ctx)
//   srow[n]   = C^-0.5/rowsum(eq)      (folded into attn epilogue)
//   ctxT' = rcp * (Vt @ Et^T)          (split-K=2 + reduce)
//   x2 = srow*(eq @ ctxT'^T) + x       (RES=2, hi/lo bf16 out)
//   out = x2 @ Wc'^T                   (3-product, KC=32; Wc'=W2W1+I hi/lo
//                                       written directly by wc_gemm)
// ---------------------------------------------------------------------------

#define SN (4096LL * 512)
#define SC (512LL * 512)

// ---------------- device buffers ----------------
__device__ __nv_bfloat16 g_xh  [16777216];
__device__ __nv_bfloat16 g_wqkv[786432];
__device__ __nv_bfloat16 g_wch [262144], g_wcl[262144];
__device__ __nv_bfloat16 g_eq  [16777216];           // [B,4096,512] exp(q) bf16
__device__ __nv_bfloat16 g_Eth [16777216], g_Vth[16777216];  // [B,512,4096]
__device__ float         g_fctx[4194304];            // 16 x [512,512] split-K slices
__device__ __nv_bfloat16 g_ctxb[2097152];
__device__ __nv_bfloat16 g_x2h [16777216], g_x2l[16777216];
__device__ float         g_rcp [4096];
__device__ float         g_srow[32768];

// ---------------- PTX helpers ----------------
__device__ __forceinline__ uint32_t s2u(const void* p) {
    uint32_t a;
    asm("{ .reg .u64 t; cvta.to.shared.u64 t, %1; cvt.u32.u64 %0, t; }" : "=r"(a) : "l"(p));
    return a;
}
__device__ __forceinline__ void cp16(uint32_t s, const void* g) {
    asm volatile("cp.async.cg.shared.global [%0], [%1], 16;" :: "r"(s), "l"(g));
}
__device__ __forceinline__ void cp_commit() {
    asm volatile("cp.async.commit_group;" ::: "memory");
}
template <int N> __device__ __forceinline__ void cp_wait() {
    asm volatile("cp.async.wait_group %0;" :: "n"(N) : "memory");
}
__device__ __forceinline__ void ldsm4(uint32_t* r, uint32_t a) {
    asm volatile("ldmatrix.sync.aligned.m8n8.x4.shared.b16 {%0,%1,%2,%3}, [%4];"
                 : "=r"(r[0]), "=r"(r[1]), "=r"(r[2]), "=r"(r[3]) : "r"(a));
}
__device__ __forceinline__ void mma16816(float* d, const uint32_t* a, const uint32_t* b) {
    asm volatile(
        "mma.sync.aligned.m16n8k16.row.col.f32.bf16.bf16.f32 "
        "{%0,%1,%2,%3}, {%4,%5,%6,%7}, {%8,%9}, {%0,%1,%2,%3};"
        : "+f"(d[0]), "+f"(d[1]), "+f"(d[2]), "+f"(d[3])
        : "r"(a[0]), "r"(a[1]), "r"(a[2]), "r"(a[3]), "r"(b[0]), "r"(b[1]));
}
__device__ __forceinline__ void split1(float v, __nv_bfloat16& h, __nv_bfloat16& l) {
    h = __float2bfloat16(v);
    l = __float2bfloat16(v - __bfloat162float(h));
}
// Conflict-free swizzles. CPR = 16B chunks per row (8 for 128B rows, 4 for 64B).
template <int CPR>
__device__ __forceinline__ uint32_t swi(int r, int c) {
    if (CPR == 8) return (uint32_t)((r * 8 + (c ^ (r & 7))) * 16);
    else          return (uint32_t)((r * 4 + (c ^ ((r >> 1) & 3))) * 16);
}

// ---------------------------------------------------------------------------
// GEMM: C[m,n] = sum_k A[m,k]*B[n,k] (+res)
// NPROD: 1 single bf16 | 3 hi/lo 3-product
// RES:   0 none | 1 fp32 Res | 2 scale acc by Srow[row] then add fp32 Res
// OM:    1 fp32 out | 2 hi/lo bf16 out | 4 single bf16 out
//        6 qkv-split: cols<512 -> exp -> Ch (stride 512); 512-1023 -> exp+T
//          to Cl; 1024+ -> T to Cf(as bf16)
// KC:    K-chunk (64 or 32). CTA 128x128, 8 warps (2m x 4n, 64x32 warp tile).
// NSTAGE=3. zshift: blockIdx.z = (batch << zshift) | kslice.
// ---------------------------------------------------------------------------
template <int NPROD, int RES, int OM, int KC>
__global__ __launch_bounds__(256, 1) void gemm_mma(
    const __nv_bfloat16* __restrict__ Ah, const __nv_bfloat16* __restrict__ Al,
    const __nv_bfloat16* __restrict__ Bh, const __nv_bfloat16* __restrict__ Bl,
    const float* __restrict__ Res, const float* __restrict__ Srow,
    float* __restrict__ Cf, __nv_bfloat16* __restrict__ Ch, __nv_bfloat16* __restrict__ Cl,
    int Ncols, int K, int ldk, int zshift,
    long long sA, long long sB, long long sRes, long long sC)
{
    constexpr int CPR = KC / 8;                       // 16B chunks per row
    constexpr uint32_t TSZ = 128u * (uint32_t)KC * 2u; // one tile bytes
    constexpr uint32_t BOFF = (NPROD == 1 ? 1u : 2u) * TSZ;
    constexpr uint32_t STAGE = BOFF + (NPROD == 1 ? 1u : 2u) * TSZ;
    extern __shared__ char smem[];
    const uint32_t su = s2u(smem);
    const int tid  = threadIdx.x;
    const int lane = tid & 31, warp = tid >> 5;
    const int wm = warp >> 2, wn = warp & 3;

    const int zb = blockIdx.z >> zshift;
    const int zs = blockIdx.z & ((1 << zshift) - 1);
    const long long koff = (long long)zs * K;
    Ah += zb * sA + koff;  Bh += zb * sB + koff;
    if (NPROD == 3) { Al += zb * sA + koff;  Bl += zb * sB + koff; }
    if (RES >= 1) Res += zb * sRes;

    const int row0 = blockIdx.y * 128;
    const int col0 = blockIdx.x * 128;

    float acc[4][4][4] = {};
    const int nch = K / KC;

    auto load_stage = [&](int ch, int s) {
        const int kb = ch * KC;
        const uint32_t sb = su + (uint32_t)s * STAGE;
        #pragma unroll
        for (int it = 0; it < CPR / 2; it++) {        // 128*CPR chunks / 256 thr
            int slot = tid + (it << 8);
            int r = slot / CPR, c = slot % CPR;
            uint32_t sw = swi<CPR>(r, c);
            long long ga = (long long)(row0 + r) * ldk + kb + c * 8;
            long long gb = (long long)(col0 + r) * ldk + kb + c * 8;
            cp16(sb + sw, Ah + ga);
            cp16(sb + BOFF + sw, Bh + gb);
            if (NPROD == 3) {
                cp16(sb + TSZ + sw, Al + ga);
                cp16(sb + BOFF + TSZ + sw, Bl + gb);
            }
        }
        cp_commit();
    };

    load_stage(0, 0);
    if (nch > 1) load_stage(1, 1);

    for (int ch = 0; ch < nch; ch++) {
        if (ch + 1 < nch) cp_wait<1>(); else cp_wait<0>();
        __syncthreads();
        if (ch + 2 < nch) load_stage(ch + 2, (ch + 2) % 3);

        const uint32_t sb  = su + (uint32_t)(ch % 3) * STAGE;
        const uint32_t sbB = sb + BOFF;
        #pragma unroll
        for (int kk = 0; kk < KC / 16; kk++) {
            uint32_t ah[4][4], al[4][4], bh[4][2], bl[4][2];
            const int ra = (lane & 7) + ((lane >> 3) & 1) * 8;
            const int cc = kk * 2 + (lane >> 4);
            #pragma unroll
            for (int i = 0; i < 4; i++) {
                uint32_t o = swi<CPR>(wm * 64 + i * 16 + ra, cc);
                ldsm4(ah[i], sb + o);
                if (NPROD == 3) ldsm4(al[i], sb + TSZ + o);
            }
            #pragma unroll
            for (int jj = 0; jj < 2; jj++) {
                uint32_t o = swi<CPR>(wn * 32 + jj * 16 + ra, cc);
                uint32_t t[4];
                ldsm4(t, sbB + o);
                bh[jj*2][0] = t[0]; bh[jj*2+1][0] = t[1];
                bh[jj*2][1] = t[2]; bh[jj*2+1][1] = t[3];
                if (NPROD == 3) {
                    ldsm4(t, sbB + TSZ + o);
                    bl[jj*2][0] = t[0]; bl[jj*2+1][0] = t[1];
                    bl[jj*2][1] = t[2]; bl[jj*2+1][1] = t[3];
                }
            }
            #pragma unroll
            for (int i = 0; i < 4; i++)
                #pragma unroll
                for (int j = 0; j < 4; j++) {
                    mma16816(acc[i][j], ah[i], bh[j]);
                    if (NPROD == 3) {
                        mma16816(acc[i][j], ah[i], bl[j]);
                        mma16816(acc[i][j], al[i], bh[j]);
                    }
                }
        }
        __syncthreads();
    }

    // epilogue
    const int g = lane >> 2, t4 = lane & 3;
    const long long ob = (long long)blockIdx.z * sC;

    if (OM == 6) {
        if (col0 < 512) {
            // q columns: exp + plain bf16 store, row stride 512
            #pragma unroll
            for (int i = 0; i < 4; i++)
                #pragma unroll
                for (int j = 0; j < 4; j++) {
                    long long r1 = (long long)(row0 + wm * 64 + i * 16 + g);
                    int cidx = col0 + wn * 32 + j * 8 + t4 * 2;
                    __nv_bfloat162 b0, b1;
                    b0.x = __float2bfloat16(expf(acc[i][j][0]));
                    b0.y = __float2bfloat16(expf(acc[i][j][1]));
                    b1.x = __float2bfloat16(expf(acc[i][j][2]));
                    b1.y = __float2bfloat16(expf(acc[i][j][3]));
                    *(__nv_bfloat162*)(Ch + (long long)zb * SN + r1 * 512 + cidx)       = b0;
                    *(__nv_bfloat162*)(Ch + (long long)zb * SN + (r1 + 8) * 512 + cidx) = b1;
                }
        } else {
            const bool isE = (col0 < 1024);
            __nv_bfloat16* stage = (__nv_bfloat16*)smem;   // [128][130]
            #pragma unroll
            for (int i = 0; i < 4; i++)
                #pragma unroll
                for (int j = 0; j < 4; j++) {
                    int rl = wm * 64 + i * 16 + g;
                    int cl = wn * 32 + j * 8 + t4 * 2;
                    float4 v = { acc[i][j][0], acc[i][j][1], acc[i][j][2], acc[i][j][3] };
                    if (isE) { v.x = expf(v.x); v.y = expf(v.y); v.z = expf(v.z); v.w = expf(v.w); }
                    __nv_bfloat162 p0, p1;
                    p0.x = __float2bfloat16(v.x); p0.y = __float2bfloat16(v.y);
                    p1.x = __float2bfloat16(v.z); p1.y = __float2bfloat16(v.w);
                    *(__nv_bfloat162*)(stage + rl * 130 + cl)       = p0;
                    *(__nv_bfloat162*)(stage + (rl + 8) * 130 + cl) = p1;
                }
            __syncthreads();
            __nv_bfloat16* dst = isE ? Cl : (__nv_bfloat16*)Cf;
            const int cb = col0 - (isE ? 512 : 1024);
            const int c = tid >> 1, half = tid & 1;
            long long base = (long long)zb * SN + (long long)(cb + c) * 4096 + row0 + half * 64;
            #pragma unroll
            for (int q8 = 0; q8 < 8; q8++) {
                alignas(16) __nv_bfloat16 t8[8];
                #pragma unroll
                for (int r = 0; r < 8; r++)
                    t8[r] = stage[(half * 64 + q8 * 8 + r) * 130 + c];
                *(uint4*)(dst + base + q8 * 8) = *(const uint4*)t8;
            }
        }
        return;
    }

    #pragma unroll
    for (int i = 0; i < 4; i++) {
        long long r1b = (long long)(row0 + wm * 64 + i * 16 + g);
        float sr0 = 1.f, sr1 = 1.f;
        if (RES == 2) {
            sr0 = Srow[(long long)zb * 4096 + r1b];
            sr1 = Srow[(long long)zb * 4096 + r1b + 8];
        }
        #pragma unroll
        for (int j = 0; j < 4; j++) {
            long long r1 = r1b;
            int cidx = col0 + wn * 32 + j * 8 + t4 * 2;
            float2 v0 = { acc[i][j][0], acc[i][j][1] };
            float2 v1 = { acc[i][j][2], acc[i][j][3] };
            if (RES == 2) {
                v0.x *= sr0; v0.y *= sr0;
                v1.x *= sr1; v1.y *= sr1;
            }
            if (RES >= 1) {
                float2 a0 = *(const float2*)(Res + r1 * Ncols + cidx);
                float2 a1 = *(const float2*)(Res + (r1 + 8) * Ncols + cidx);
                v0.x += a0.x; v0.y += a0.y;
                v1.x += a1.x; v1.y += a1.y;
            }
            if (OM == 1) {
                *(float2*)(Cf + ob + r1 * Ncols + cidx)       = v0;
                *(float2*)(Cf + ob + (r1 + 8) * Ncols + cidx) = v1;
            }
            if (OM == 2) {
                __nv_bfloat16 h, l;
                __nv_bfloat162 h0, l0, h1, l1;
                split1(v0.x, h, l); h0.x = h; l0.x = l;
                split1(v0.y, h, l); h0.y = h; l0.y = l;
                split1(v1.x, h, l); h1.x = h; l1.x = l;
                split1(v1.y, h, l); h1.y = h; l1.y = l;
                *(__nv_bfloat162*)(Ch + ob + r1 * Ncols + cidx)       = h0;
                *(__nv_bfloat162*)(Ch + ob + (r1 + 8) * Ncols + cidx) = h1;
                *(__nv_bfloat162*)(Cl + ob + r1 * Ncols + cidx)       = l0;
                *(__nv_bfloat162*)(Cl + ob + (r1 + 8) * Ncols + cidx) = l1;
            }
            if (OM == 4) {
                __nv_bfloat162 b0, b1;
                b0.x = __float2bfloat16(v0.x); b0.y = __float2bfloat16(v0.y);
                b1.x = __float2bfloat16(v1.x); b1.y = __float2bfloat16(v1.y);
                *(__nv_bfloat162*)(Ch + ob + r1 * Ncols + cidx)       = b0;
                *(__nv_bfloat162*)(Ch + ob + (r1 + 8) * Ncols + cidx) = b1;
            }
        }
    }
}

// ---------------------------------------------------------------------------
// Wc' = W2 @ W1 + I in fp32, hi/lo bf16 written directly. 512^3, tiny.
// ---------------------------------------------------------------------------
__global__ __launch_bounds__(256) void wc_gemm(
    const float* __restrict__ W2, const float* __restrict__ W1,
    __nv_bfloat16* __restrict__ Wh, __nv_bfloat16* __restrict__ Wl)
{
    __shared__ float As[16][64];
    __shared__ float Bs[16][68];
    const int tx = threadIdx.x, ty = threadIdx.y;
    const int tid = ty * 16 + tx;
    const int n0 = blockIdx.y * 64, k0 = blockIdx.x * 64;
    float acc[4][4] = {};

    for (int jb = 0; jb < 512; jb += 16) {
        int r = tid >> 2, q = tid & 3;
        float4 va = *(const float4*)(W2 + (n0 + r) * 512 + jb + q * 4);
        As[q*4+0][r] = va.x; As[q*4+1][r] = va.y;
        As[q*4+2][r] = va.z; As[q*4+3][r] = va.w;
        int rr = tid >> 4, cc = tid & 15;
        *(float4*)&Bs[rr][cc*4] = *(const float4*)(W1 + (jb + rr) * 512 + k0 + cc * 4);
        __syncthreads();
        #pragma unroll
        for (int j = 0; j < 16; j++) {
            float a[4], b[4];
            #pragma unroll
            for (int i = 0; i < 4; i++) a[i] = As[j][ty * 4 + i];
            #pragma unroll
            for (int jx = 0; jx < 4; jx++) b[jx] = Bs[j][tx * 4 + jx];
            #pragma unroll
            for (int i = 0; i < 4; i++)
                #pragma unroll
                for (int jx = 0; jx < 4; jx++)
                    acc[i][jx] = fmaf(a[i], b[jx], acc[i][jx]);
        }
        __syncthreads();
    }
    #pragma unroll
    for (int i = 0; i < 4; i++)
        #pragma unroll
        for (int jx = 0; jx < 4; jx++) {
            int rn = n0 + ty * 4 + i, rk = k0 + tx * 4 + jx;
            float v = acc[i][jx] + ((rn == rk) ? 1.0f : 0.0f);
            __nv_bfloat16 h, l;
            split1(v, h, l);
            Wh[(long long)rn * 512 + rk] = h;
            Wl[(long long)rn * 512 + rk] = l;
        }
}

// ---------------- elementwise ----------------
__global__ void cvt_b(const float* __restrict__ in, __nv_bfloat16* __restrict__ ob, int n4)
{
    int i = blockIdx.x * 256 + threadIdx.x;
    if (i >= n4) return;
    float4 v = ((const float4*)in)[i];
    __nv_bfloat162 p0, p1;
    p0.x = __float2bfloat16(v.x); p0.y = __float2bfloat16(v.y);
    p1.x = __float2bfloat16(v.z); p1.y = __float2bfloat16(v.w);
    ((__nv_bfloat162*)ob)[2*i]   = p0;
    ((__nv_bfloat162*)ob)[2*i+1] = p1;
}

// reduce split-K ctx slices with rcp fold: ctxb = bf16(rcp[d] * (f0 + f1))
__global__ void reduce_ctx(const float* __restrict__ f, const float* __restrict__ rcp,
                           __nv_bfloat16* __restrict__ ob)
{
    int i = blockIdx.x * 256 + threadIdx.x;
    int b = i >> 16;
    int r = i & 65535;
    int d = (r * 4) & 511;                       // column within ctxT row
    const float4* p0 = (const float4*)(f + (long long)(2 * b) * SC) + r;
    const float4* p1 = (const float4*)(f + (long long)(2 * b + 1) * SC) + r;
    float4 a = *p0, c = *p1;
    float4 rc = *(const float4*)(rcp + b * 512 + d);
    __nv_bfloat162 q0, q1;
    q0.x = __float2bfloat16((a.x + c.x) * rc.x); q0.y = __float2bfloat16((a.y + c.y) * rc.y);
    q1.x = __float2bfloat16((a.z + c.z) * rc.z); q1.y = __float2bfloat16((a.w + c.w) * rc.w);
    ((__nv_bfloat162*)(ob + (long long)b * SC))[2*r]   = q0;
    ((__nv_bfloat162*)(ob + (long long)b * SC))[2*r+1] = q1;
}

// rcp[row] = 1 / sum(Eth[row, :]) ; Eth rows contiguous [B*512, 4096]
__global__ void rowsum_rcp(const __nv_bfloat16* __restrict__ Eth, float* __restrict__ rcp)
{
    __shared__ float red[4];
    long long row = blockIdx.x;
    const __nv_bfloat162* p = (const __nv_bfloat162*)(Eth + row * 4096);
    int t = threadIdx.x;                       // 128 threads
    float s = 0.f;
    #pragma unroll 4
    for (int i = t; i < 2048; i += 128) {
        __nv_bfloat162 v = p[i];
        s += __bfloat162float(v.x) + __bfloat162float(v.y);
    }
    #pragma unroll
    for (int o = 16; o; o >>= 1) s += __shfl_xor_sync(0xffffffffu, s, o);
    if ((t & 31) == 0) red[t >> 5] = s;
    __syncthreads();
    if (t == 0) rcp[row] = 1.0f / (red[0] + red[1] + red[2] + red[3]);
}

// srow[row] = C^-0.5 / sum(eq[row, :]) ; eq rows contiguous [B*4096, 512]
__global__ void rowsum_q(const __nv_bfloat16* __restrict__ eq, float* __restrict__ srow)
{
    __shared__ float red[4];
    long long row = blockIdx.x;                // 0..32767
    const __nv_bfloat162* p = (const __nv_bfloat162*)(eq + row * 512);
    int t = threadIdx.x;                       // 128 threads
    __nv_bfloat162 v0 = p[2*t], v1 = p[2*t+1];
    float s = __bfloat162float(v0.x) + __bfloat162float(v0.y)
            + __bfloat162float(v1.x) + __bfloat162float(v1.y);
    #pragma unroll
    for (int o = 16; o; o >>= 1) s += __shfl_xor_sync(0xffffffffu, s, o);
    if ((t & 31) == 0) red[t >> 5] = s;
    __syncthreads();
    if (t == 0) srow[row] = 0.044194173824159216f / (red[0] + red[1] + red[2] + red[3]);
}

// ---------------- host ----------------
extern "C" void kernel_launch(void* const* d_in, const int* in_sizes, int n_in,
                              void* d_out, int out_size)
{
    const float* x  = (const float*)d_in[0];
    const float* Wq = (const float*)d_in[1];
    const float* Wk = (const float*)d_in[2];
    const float* Wv = (const float*)d_in[3];
    const float* W1 = (const float*)d_in[4];
    const float* W2 = (const float*)d_in[5];
    float* out = (float*)d_out;

    __nv_bfloat16 *xh,*wqkv,*wch,*wcl,*eq,*Eth,*Vth,*ctxb,*x2h,*x2l;
    float *fctx,*rcp,*srow;
    cudaGetSymbolAddress((void**)&xh, g_xh);
    cudaGetSymbolAddress((void**)&wqkv, g_wqkv);
    cudaGetSymbolAddress((void**)&wch, g_wch); cudaGetSymbolAddress((void**)&wcl, g_wcl);
    cudaGetSymbolAddress((void**)&eq, g_eq);
    cudaGetSymbolAddress((void**)&Eth, g_Eth); cudaGetSymbolAddress((void**)&Vth, g_Vth);
    cudaGetSymbolAddress((void**)&fctx, g_fctx);
    cudaGetSymbolAddress((void**)&ctxb, g_ctxb);
    cudaGetSymbolAddress((void**)&x2h, g_x2h); cudaGetSymbolAddress((void**)&x2l, g_x2l);
    cudaGetSymbolAddress((void**)&rcp, g_rcp);
    cudaGetSymbolAddress((void**)&srow, g_srow);

    cudaFuncSetAttribute((const void*)gemm_mma<1,0,6,64>, cudaFuncAttributeMaxDynamicSharedMemorySize, 98304);
    cudaFuncSetAttribute((const void*)gemm_mma<1,0,1,64>, cudaFuncAttributeMaxDynamicSharedMemorySize, 98304);
    cudaFuncSetAttribute((const void*)gemm_mma<1,2,2,64>, cudaFuncAttributeMaxDynamicSharedMemorySize, 98304);
    cudaFuncSetAttribute((const void*)gemm_mma<3,0,1,32>, cudaFuncAttributeMaxDynamicSharedMemorySize, 98304);

    // prep
    wc_gemm<<<dim3(8, 8), dim3(16, 16)>>>(W2, W1, wch, wcl);
    cvt_b<<<256, 256>>>(Wq, wqkv,          65536);
    cvt_b<<<256, 256>>>(Wk, wqkv + 262144, 65536);
    cvt_b<<<256, 256>>>(Wv, wqkv + 524288, 65536);
    cvt_b<<<16384, 256>>>(x, xh, 4194304);

    // fused qkv projection -> eq | Eth(exp,T) | Vth(T)   (OM=6)
    gemm_mma<1,0,6,64><<<dim3(12, 32, 8), 256, 98304>>>(xh, nullptr, wqkv, nullptr,
        nullptr, nullptr, (float*)Vth, eq, Eth, 1536, 512, 512, 0, SN, 0, 0, SN);

    // softmax normalizers
    rowsum_rcp<<<4096, 128>>>(Eth, rcp);
    rowsum_q<<<32768, 128>>>(eq, srow);

    // ctxT[e,d] = sum_n Vt[e,n]*Et[d,n], split-K=2 -> fp32 slices -> reduce(*rcp)
    gemm_mma<1,0,1,64><<<dim3(4, 4, 16), 256, 98304>>>(Vth, nullptr, Eth, nullptr,
        nullptr, nullptr, fctx, nullptr, nullptr, 512, 2048, 4096, 1, SN, SN, 0, SC);
    reduce_ctx<<<2048, 256>>>(fctx, rcp, ctxb);

    // x2 = srow*(eq @ ctxT'^T) + x  -> hi/lo bf16   (RES=2)
    gemm_mma<1,2,2,64><<<dim3(4, 32, 8), 256, 98304>>>(eq, nullptr, ctxb, nullptr,
        x, srow, nullptr, x2h, x2l, 512, 512, 512, 0, SN, SC, SN, SN);

    // out = x2 @ Wc'^T   (3-product, KC=32, 2 CTAs/SM)
    gemm_mma<3,0,1,32><<<dim3(4, 32, 8), 256, 98304>>>(x2h, x2l, wch, wcl,
        nullptr, nullptr, out, nullptr, nullptr, 512, 512, 512, 0, SN, 0, 0, SN);
}